// round 17
// baseline (speedup 1.0000x reference)
#include <cuda_runtime.h>
#include <cuda_fp16.h>
#include <math.h>
#include <stdint.h>

#define BDIM 2
#define SEQ  2048
#define HID  2048
#define NH   8
#define HD   256
#define HALF 128

#define BM 128
#define BN 128
#define BK 32
#define STAGES 3

typedef __half fp16;

// ------------------------- static device scratch ---------------------------
__device__ __align__(16) float g_qraw[BDIM*SEQ*NH*HD];
__device__ __align__(16) float g_kraw[BDIM*SEQ*HD];
__device__ __align__(16) float g_attn_s[(size_t)BDIM*NH*SEQ*SEQ];
__device__ __align__(16) float g_rsum[BDIM*NH*SEQ];

__device__ __align__(16) fp16 g_hid[BDIM*SEQ*HID];
__device__ __align__(16) fp16 g_wqkv[HID*(NH*HD + 2*HD)];  // [2048, 2560] Wq|Wk|Wv
__device__ __align__(16) fp16 g_wo[NH*HD*HID];             // [2048, 2048]
__device__ __align__(16) fp16 g_q[BDIM*NH*SEQ*HD];
__device__ __align__(16) fp16 g_k[BDIM*SEQ*HD];
__device__ __align__(16) fp16 g_v[BDIM*SEQ*HD];
__device__ __align__(16) fp16 g_at[(size_t)BDIM*NH*SEQ*SEQ];   // unnormalized exp plane
__device__ __align__(16) fp16 g_ah[BDIM*SEQ*NH*HD];

// ------------------------------- helpers -----------------------------------
__device__ __forceinline__ uint32_t smem_u32(const void* p) {
    return (uint32_t)__cvta_generic_to_shared(p);
}
__device__ __forceinline__ void cp16a(void* dst, const void* src) {
    asm volatile("cp.async.cg.shared.global [%0], [%1], 16;\n"
                 :: "r"(smem_u32(dst)), "l"(src));
}
__device__ __forceinline__ void cp_commit() { asm volatile("cp.async.commit_group;\n"); }
template<int N> __device__ __forceinline__ void cp_wait() {
    asm volatile("cp.async.wait_group %0;\n" :: "n"(N));
}
__device__ __forceinline__ void ldm4(uint32_t r[4], uint32_t a) {
    asm volatile("ldmatrix.sync.aligned.m8n8.x4.shared.b16 {%0,%1,%2,%3}, [%4];\n"
                 : "=r"(r[0]), "=r"(r[1]), "=r"(r[2]), "=r"(r[3]) : "r"(a));
}
__device__ __forceinline__ void ldm4t(uint32_t r[4], uint32_t a) {
    asm volatile("ldmatrix.sync.aligned.m8n8.x4.trans.shared.b16 {%0,%1,%2,%3}, [%4];\n"
                 : "=r"(r[0]), "=r"(r[1]), "=r"(r[2]), "=r"(r[3]) : "r"(a));
}
__device__ __forceinline__ void mma_fp16(float c[4], const uint32_t a[4],
                                         uint32_t b0, uint32_t b1) {
    asm volatile(
        "mma.sync.aligned.m16n8k16.row.col.f32.f16.f16.f32 "
        "{%0,%1,%2,%3}, {%4,%5,%6,%7}, {%8,%9}, {%0,%1,%2,%3};\n"
        : "+f"(c[0]), "+f"(c[1]), "+f"(c[2]), "+f"(c[3])
        : "r"(a[0]), "r"(a[1]), "r"(a[2]), "r"(a[3]), "r"(b0), "r"(b1));
}
__device__ __forceinline__ uint32_t pack2h(float a, float b) {
    __half2 v = __floats2half2_rn(a, b);
    return *(uint32_t*)&v;
}
__device__ __forceinline__ uint2 f4h4(float4 v) {
    uint2 r; r.x = pack2h(v.x, v.y); r.y = pack2h(v.z, v.w); return r;
}

// ---------------------------------------------------------------------------
// fp16 GEMM (single or 2-pass A hi/lo; Al may be nullptr).
// NT=false: B [K,N] row-major.  NT=true: B [N,K] row-major (C = A·B^T).
// epi: 0 f32 C (ldc); 3 fp16 single Ch (ldc);
//      4 QKV triple: n0<2048 f32 C (ldc 2048); [2048,2304) f32 C2 (ldc 256);
//        >=2304 fp16 Ch (ldc 256);
//      5 PV: bx<2 GEMM -> fp16 Ch scaled by 1/rowsum; bx==2 normalize CTAs:
//        C[row][j] = Ah[row][j]/rowsum[row] (f32, zero tail) — fused normalize;
//      6 scores: e=exp(logit), causal mask, fp16 Ch + rowsum atomicAdd.
// cmode: 0 none; 1 (NT) causal tile-skip; 2 causal K-limit.
// 256 threads, warps 2(m) x 4(n), warp tile 64x32, 3-stage cp.async.
// ---------------------------------------------------------------------------
template<bool NT>
__global__ __launch_bounds__(256, 2) void gemm2p(
    const fp16* __restrict__ Ah, const fp16* __restrict__ Al,
    const fp16* __restrict__ Bs,
    float* __restrict__ C, float* __restrict__ C2, fp16* __restrict__ Ch,
    float* __restrict__ RS,
    int K, int lda, int ldb, int ldc,
    int zdiv, long long Ao, long long Ai, long long Bo, long long Bi,
    long long Co, long long Ci, int cmode, int epi)
{
    if (NT && cmode == 1 && blockIdx.x > blockIdx.y) return;

    constexpr int ASTR  = BK + 8;                  // 40
    constexpr int BROWS = NT ? BN : BK;
    constexpr int BSTR  = NT ? (BK + 8) : (BN + 8);
    constexpr int AELEM = BM * ASTR;               // 5120
    constexpr int BELEM = BROWS * BSTR;

    extern __shared__ fp16 smem[];
    const bool has_lo = (Al != nullptr);
    fp16* pAh = smem;
    fp16* pAl = pAh + STAGES * AELEM;
    fp16* pB  = has_lo ? (pAl + STAGES * AELEM) : pAl;

    int z = blockIdx.z;
    int zo = z / zdiv, zi = z - zo * zdiv;
    Ah += zo * Ao + zi * Ai;
    if (has_lo) Al += zo * Ao + zi * Ai;
    Bs += zo * Bo + zi * Bi;
    long long coff = zo * Co + zi * Ci;

    int m0 = blockIdx.y * BM, n0 = blockIdx.x * BN;
    int tid = threadIdx.x, lane = tid & 31, wid = tid >> 5;
    int wm = wid & 1, wn = wid >> 1;

    // ---- fused-normalize CTAs in the PV launch (epi 5, bx == 2) ----
    if (epi == 5 && blockIdx.x == 2) {
        const float* rsum = RS + (size_t)z * SEQ;
        size_t zoff = (size_t)(zo * Ao + zi * Ai);   // attn shares at's z layout
        int lim = ((int)blockIdx.y + 1) * BM;        // causal span for this m-tile
        int r = tid >> 1, half = tid & 1;
        int row = m0 + r;
        float inv = 1.f / rsum[row];
        const fp16* re = Ah + (size_t)row * SEQ;     // Ah already z-offset
        float* ro = C + zoff + (size_t)row * SEQ;
        int j0 = half * (SEQ / 2), j1 = j0 + (SEQ / 2);
        for (int j = j0; j < j1; j += 4) {
            if (j < lim) {
                uint2 hv = *(const uint2*)(re + j);
                float2 a = __half22float2(*(__half2*)&hv.x);
                float2 b = __half22float2(*(__half2*)&hv.y);
                *(float4*)(ro + j) = make_float4(a.x * inv, a.y * inv, b.x * inv, b.y * inv);
            } else {
                *(float4*)(ro + j) = make_float4(0.f, 0.f, 0.f, 0.f);
            }
        }
        return;
    }

    int kmax = (cmode == 2) ? min(K, m0 + BM) : K;
    int niter = kmax / BK;

    const int ar0 = tid >> 2,         ac0 = (tid & 3) * 8;
    const int ar1 = (tid + 256) >> 2, ac1 = ac0;
    const int br0 = tid >> 4,         bc0 = (tid & 15) * 8;
    const int br1 = (tid + 256) >> 4, bc1 = bc0;

    float c[4][4][4];
#pragma unroll
    for (int mt = 0; mt < 4; mt++)
#pragma unroll
        for (int nt = 0; nt < 4; nt++)
#pragma unroll
            for (int i = 0; i < 4; i++) c[mt][nt][i] = 0.f;

    auto load_stage = [&](int st, int k0) {
        fp16* ah = pAh + st * AELEM;  fp16* al = pAl + st * AELEM;
        fp16* bb = pB  + st * BELEM;
        cp16a(ah + ar0 * ASTR + ac0, Ah + (size_t)(m0 + ar0) * lda + k0 + ac0);
        cp16a(ah + ar1 * ASTR + ac1, Ah + (size_t)(m0 + ar1) * lda + k0 + ac1);
        if (has_lo) {
            cp16a(al + ar0 * ASTR + ac0, Al + (size_t)(m0 + ar0) * lda + k0 + ac0);
            cp16a(al + ar1 * ASTR + ac1, Al + (size_t)(m0 + ar1) * lda + k0 + ac1);
        }
        if (NT) {
            cp16a(bb + ar0 * BSTR + ac0, Bs + (size_t)(n0 + ar0) * ldb + k0 + ac0);
            cp16a(bb + ar1 * BSTR + ac1, Bs + (size_t)(n0 + ar1) * ldb + k0 + ac1);
        } else {
            cp16a(bb + br0 * BSTR + bc0, Bs + (size_t)(k0 + br0) * ldb + n0 + bc0);
            cp16a(bb + br1 * BSTR + bc1, Bs + (size_t)(k0 + br1) * ldb + n0 + bc1);
        }
    };

    auto load_fb = [&](uint32_t* fb, const fp16* bb, int ks) {
#pragma unroll
        for (int p = 0; p < 2; p++) {
            if (NT) {
                int row = wn * 32 + p * 16 + (lane & 7) + ((lane >> 4) << 3);
                int col = ks + (lane & 8);
                ldm4(&fb[4 * p], smem_u32(bb + row * BSTR + col));
            } else {
                int row = ks + (lane & 15);
                int col = wn * 32 + p * 16 + ((lane >> 4) << 3);
                ldm4t(&fb[4 * p], smem_u32(bb + row * BSTR + col));
            }
        }
    };
    auto load_fa = [&](uint32_t fa[4][4], const fp16* ap, int ks) {
#pragma unroll
        for (int mt = 0; mt < 4; mt++) {
            int row = wm * 64 + mt * 16 + (lane & 15);
            int col = ks + ((lane >> 4) << 3);
            ldm4(fa[mt], smem_u32(ap + row * ASTR + col));
        }
    };
    auto do_mma = [&](uint32_t fa[4][4], const uint32_t* fb) {
#pragma unroll
        for (int mt = 0; mt < 4; mt++)
#pragma unroll
            for (int nt = 0; nt < 4; nt++)
                mma_fp16(c[mt][nt], fa[mt], fb[2*nt], fb[2*nt+1]);
    };

#pragma unroll
    for (int s = 0; s < STAGES - 1; s++) {
        if (s < niter) load_stage(s, s * BK);
        cp_commit();
    }

    for (int it = 0; it < niter; it++) {
        cp_wait<STAGES - 2>();
        __syncthreads();

        int nk = it + STAGES - 1;
        if (nk < niter) load_stage(nk % STAGES, nk * BK);
        cp_commit();

        int st = it % STAGES;
        const fp16* ah = pAh + st * AELEM;
        const fp16* al = pAl + st * AELEM;
        const fp16* bb = pB  + st * BELEM;

        uint32_t fb0[8], fb1[8], fa[4][4];
        load_fb(fb0, bb, 0);
        load_fa(fa, ah, 0);
        load_fb(fb1, bb, 16);
        do_mma(fa, fb0);
        load_fa(fa, ah, 16);
        do_mma(fa, fb1);
        if (has_lo) {
            load_fa(fa, al, 0);
            do_mma(fa, fb0);
            load_fa(fa, al, 16);
            do_mma(fa, fb1);
        }
        __syncthreads();
    }

    // ============================= epilogues =============================
    if (epi == 6) {
        cp_wait<0>();
        __syncthreads();
        float* rs = (float*)smem;                   // overlay [4][128]
        float* rsum = RS + (size_t)z * SEQ;
#pragma unroll
        for (int mt = 0; mt < 4; mt++) {
            int lrow0 = wm * 64 + mt * 16 + (lane >> 2);
            int grow0 = m0 + lrow0;
            float ps0 = 0.f, ps1 = 0.f;
#pragma unroll
            for (int nt = 0; nt < 4; nt++) {
                int gcol = n0 + wn * 32 + nt * 8 + (lane & 3) * 2;
                float e0 = (gcol     <= grow0)     ? __expf(c[mt][nt][0]) : 0.f;
                float e1 = (gcol + 1 <= grow0)     ? __expf(c[mt][nt][1]) : 0.f;
                float e2 = (gcol     <= grow0 + 8) ? __expf(c[mt][nt][2]) : 0.f;
                float e3 = (gcol + 1 <= grow0 + 8) ? __expf(c[mt][nt][3]) : 0.f;
                size_t o0 = (size_t)coff + (size_t)grow0 * ldc + gcol;
                *(uint32_t*)(Ch + o0)                    = pack2h(e0, e1);
                *(uint32_t*)(Ch + o0 + 8 * (size_t)ldc) = pack2h(e2, e3);
                ps0 += e0 + e1; ps1 += e2 + e3;
            }
            ps0 += __shfl_xor_sync(0xffffffffu, ps0, 1);
            ps0 += __shfl_xor_sync(0xffffffffu, ps0, 2);
            ps1 += __shfl_xor_sync(0xffffffffu, ps1, 1);
            ps1 += __shfl_xor_sync(0xffffffffu, ps1, 2);
            if ((lane & 3) == 0) {
                rs[wn * 128 + lrow0]     = ps0;
                rs[wn * 128 + lrow0 + 8] = ps1;
            }
        }
        __syncthreads();
        if (tid < 128) {
            float s = rs[tid] + rs[128 + tid] + rs[256 + tid] + rs[384 + tid];
            atomicAdd(&rsum[m0 + tid], s);
        }
        return;
    }
    if (epi == 5) {
        const float* rsum = RS + (size_t)z * SEQ;
#pragma unroll
        for (int mt = 0; mt < 4; mt++) {
            int row = m0 + wm * 64 + mt * 16 + (lane >> 2);
            float inv0 = 1.f / rsum[row];
            float inv1 = 1.f / rsum[row + 8];
#pragma unroll
            for (int nt = 0; nt < 4; nt++) {
                int col = n0 + wn * 32 + nt * 8 + (lane & 3) * 2;
                size_t o0 = (size_t)coff + (size_t)row * ldc + col;
                *(uint32_t*)(Ch + o0) = pack2h(c[mt][nt][0] * inv0, c[mt][nt][1] * inv0);
                *(uint32_t*)(Ch + o0 + 8 * (size_t)ldc) =
                    pack2h(c[mt][nt][2] * inv1, c[mt][nt][3] * inv1);
            }
        }
        return;
    }

    // generic modes 0 / 3 / 4
    int mode = epi;
    int nbase = n0;
    int ld = ldc;
    float* Cf = C;
    if (epi == 4) {
        if (n0 < 2048)      { mode = 0; ld = 2048; }
        else if (n0 < 2304) { mode = 0; Cf = C2; ld = 256; nbase = n0 - 2048; }
        else                { mode = 3; ld = 256; nbase = n0 - 2304; }
    }
#pragma unroll
    for (int mt = 0; mt < 4; mt++)
#pragma unroll
        for (int nt = 0; nt < 4; nt++) {
            int row = m0 + wm * 64 + mt * 16 + (lane >> 2);
            int col = nbase + wn * 32 + nt * 8 + (lane & 3) * 2;
            size_t o0 = (size_t)coff + (size_t)row * ld + col;
            size_t o1 = (size_t)coff + (size_t)(row + 8) * ld + col;
            float f0 = c[mt][nt][0], f1 = c[mt][nt][1];
            float f2 = c[mt][nt][2], f3 = c[mt][nt][3];
            if (mode == 0) {
                *(float2*)(Cf + o0) = make_float2(f0, f1);
                *(float2*)(Cf + o1) = make_float2(f2, f3);
            } else {  // mode 3
                *(uint32_t*)(Ch + o0) = pack2h(f0, f1);
                *(uint32_t*)(Ch + o1) = pack2h(f2, f3);
            }
        }
}

// ---------------------------------------------------------------------------
// Vectorized (x4) input conversions + rowsum zeroing, one kernel.
// ---------------------------------------------------------------------------
#define CVN0 (BDIM*SEQ*HID)
#define CVN1 (HID*NH*HD)
#define CVN2 (HID*HD)
#define CV4_0 (CVN0/4)
#define CV4_1 (CVN1/4)
#define CV4_2 (CVN2/4)
#define RSN4  (BDIM*NH*SEQ/4)
#define CV4TOT (CV4_0 + CV4_1 + 2*CV4_2 + CV4_1 + RSN4)

__global__ void conv_all(const float* __restrict__ hidden,
                         const float* __restrict__ Wq, const float* __restrict__ Wk,
                         const float* __restrict__ Wv, const float* __restrict__ Wo,
                         fp16* __restrict__ hid, fp16* __restrict__ wqkv,
                         fp16* __restrict__ wo, float* __restrict__ rsum)
{
    int t = blockIdx.x * 256 + threadIdx.x;
    if (t < CV4_0) { ((uint2*)hid)[t] = f4h4(((const float4*)hidden)[t]); return; }
    t -= CV4_0;
    if (t < CV4_1) {
        int i4 = t * 4, r = i4 >> 11, c0 = i4 & 2047;
        *(uint2*)(wqkv + (size_t)r * 2560 + c0) = f4h4(((const float4*)Wq)[t]);
        return;
    }
    t -= CV4_1;
    if (t < CV4_2) {
        int i4 = t * 4, r = i4 >> 8, c0 = i4 & 255;
        *(uint2*)(wqkv + (size_t)r * 2560 + 2048 + c0) = f4h4(((const float4*)Wk)[t]);
        return;
    }
    t -= CV4_2;
    if (t < CV4_2) {
        int i4 = t * 4, r = i4 >> 8, c0 = i4 & 255;
        *(uint2*)(wqkv + (size_t)r * 2560 + 2304 + c0) = f4h4(((const float4*)Wv)[t]);
        return;
    }
    t -= CV4_2;
    if (t < CV4_1) { ((uint2*)wo)[t] = f4h4(((const float4*)Wo)[t]); return; }
    t -= CV4_1;
    if (t < RSN4) ((float4*)rsum)[t] = make_float4(0.f, 0.f, 0.f, 0.f);
}

// ---------------------------------------------------------------------------
// RoPE: qraw [B,S,H,D] -> q fp16 [B,H,S,D] (scaled 1/16); kraw -> k fp16
// ---------------------------------------------------------------------------
__global__ void rope_conv(const int* __restrict__ pos,
                          fp16* __restrict__ q, fp16* __restrict__ k)
{
    int t = blockIdx.x * 256 + threadIdx.x;
    const int TOT = BDIM * SEQ * (NH + 1) * HALF;
    if (t >= TOT) return;
    int i = t & (HALF - 1);
    int rest = t >> 7;
    int hh = rest % (NH + 1); rest /= (NH + 1);
    int s = rest % SEQ;
    int b = rest / SEQ;

    float p = (float)pos[b * SEQ + s];
    float freq = powf(10000.f, -(float)(2 * i) / (float)HD);
    float ang = p * freq;
    float sn, cs;
    sincosf(ang, &sn, &cs);

    if (hh < NH) {
        size_t base = ((size_t)(b * SEQ + s) * NH + hh) * HD;
        float x0 = g_qraw[base + i] * 0.0625f;
        float x1 = g_qraw[base + i + HALF] * 0.0625f;
        size_t ob = ((size_t)(b * NH + hh) * SEQ + s) * HD;
        q[ob + i]        = __float2half_rn(x0 * cs - x1 * sn);
        q[ob + i + HALF] = __float2half_rn(x1 * cs + x0 * sn);
    } else {
        size_t base = (size_t)(b * SEQ + s) * HD;
        float x0 = g_kraw[base + i];
        float x1 = g_kraw[base + i + HALF];
        k[base + i]        = __float2half_rn(x0 * cs - x1 * sn);
        k[base + i + HALF] = __float2half_rn(x1 * cs + x0 * sn);
    }
}

// ---------------------------------------------------------------------------
// Host launcher
// ---------------------------------------------------------------------------
extern "C" void kernel_launch(void* const* d_in, const int* in_sizes, int n_in,
                              void* d_out, int out_size)
{
    const float* hidden = (const float*)d_in[0];
    const float* Wq     = (const float*)d_in[1];
    const float* Wk     = (const float*)d_in[2];
    const float* Wv     = (const float*)d_in[3];
    const float* Wo     = (const float*)d_in[4];
    const int*   pos    = (const int*)d_in[6];

    float *qraw, *kraw, *attn_s, *rsum;
    fp16 *hid, *wqkv, *wo, *q, *k, *v, *at, *ah;

    cudaGetSymbolAddress((void**)&qraw, g_qraw);
    cudaGetSymbolAddress((void**)&kraw, g_kraw);
    cudaGetSymbolAddress((void**)&attn_s, g_attn_s);
    cudaGetSymbolAddress((void**)&rsum, g_rsum);
    cudaGetSymbolAddress((void**)&hid, g_hid);
    cudaGetSymbolAddress((void**)&wqkv, g_wqkv);
    cudaGetSymbolAddress((void**)&wo,  g_wo);
    cudaGetSymbolAddress((void**)&q,   g_q);
    cudaGetSymbolAddress((void**)&k,   g_k);
    cudaGetSymbolAddress((void**)&v,   g_v);
    cudaGetSymbolAddress((void**)&at,  g_at);
    cudaGetSymbolAddress((void**)&ah,  g_ah);

    float* out = (float*)d_out;
    const long long OUTE  = (long long)BDIM * SEQ * HID;
    const long long ATTNE = (long long)BDIM * NH * SEQ * SEQ;
    float* attn = ((long long)out_size >= OUTE + ATTNE) ? (out + OUTE) : attn_s;

    const int M = BDIM * SEQ;  // 4096

    const int AEL = BM * (BK + 8);            // 5120 elems
    const int BEL_NN = BK * (BN + 8);         // 4352 elems
    const int SM_NN1 = STAGES * (AEL + BEL_NN) * 2;        // 56832
    const int SM_NT1 = STAGES * (2 * AEL) * 2;             // 61440
    cudaFuncSetAttribute(gemm2p<false>, cudaFuncAttributeMaxDynamicSharedMemorySize, SM_NN1);
    cudaFuncSetAttribute(gemm2p<true>,  cudaFuncAttributeMaxDynamicSharedMemorySize, SM_NT1);

    // 1: conversions + rowsum zeroing
    conv_all<<<(CV4TOT + 255) / 256, 256>>>(hidden, Wq, Wk, Wv, Wo, hid, wqkv, wo, rsum);

    // 2: merged QKV projection (single-pass, N=2560)
    gemm2p<false><<<dim3(2560/BN, M/BM, 1), 256, SM_NN1>>>(
        hid, nullptr, wqkv, qraw, kraw, v, nullptr,
        HID, HID, 2560, HID, 1, 0,0,0,0,0,0, 0, 4);

    // 3: RoPE
    { int TOT = BDIM*SEQ*(NH+1)*HALF; rope_conv<<<(TOT+255)/256, 256>>>(pos, q, k); }

    // 4: scores = q @ k^T, fused exp + rowsum -> fp16 e-plane
    gemm2p<true><<<dim3(SEQ/BN, SEQ/BM, BDIM*NH), 256, SM_NT1>>>(
        q, nullptr, k, nullptr, nullptr, at, rsum,
        HD, HD, HD, SEQ,
        NH,
        (long long)NH*SEQ*HD, (long long)SEQ*HD,
        (long long)SEQ*HD, 0,
        (long long)NH*SEQ*SEQ, (long long)SEQ*SEQ,
        1, 6);

    // 5: PV (bx<2: GEMM -> fp16 ah; bx==2: fused normalize -> f32 attn)
    gemm2p<false><<<dim3(3, SEQ/BM, BDIM*NH), 256, SM_NN1>>>(
        at, nullptr, v, attn, nullptr, ah, rsum,
        SEQ, SEQ, HD, NH*HD,
        NH,
        (long long)NH*SEQ*SEQ, (long long)SEQ*SEQ,
        (long long)SEQ*HD, 0,
        (long long)SEQ*NH*HD, (long long)HD,
        2, 5);

    // 6: out = ah @ Wo (single-pass)
    gemm2p<false><<<dim3(HID/BN, M/BM, 1), 256, SM_NN1>>>(
        ah, nullptr, wo, out, nullptr, nullptr, nullptr,
        NH*HD, NH*HD, HID, HID, 1, 0,0,0,0,0,0, 0, 0);
}